// round 1
// baseline (speedup 1.0000x reference)
#include <cuda_runtime.h>
#include <math.h>

// Problem constants
#define C_DIM   256
#define M_DIM   512
#define HW_DIM  4096      // 64*64
#define N_IMG   16
#define TB      64        // tokens per block
#define THREADS 256
#define CCHUNK  64        // c-chunk for GEMM1 tiles
#define SROW    513       // padded score row (avoids 512-stride bank conflicts)

// Normalized memory (after MLP), computed by kernel 1.
__device__ float g_mem_norm[M_DIM * C_DIM];

// ---------------------------------------------------------------------------
// Kernel 1: per-slot MLP (Linear->ReLU->Linear->ReLU) + L2 normalize.
// One block per memory slot. Trivial cost (512 slots x 64K FMA).
// ---------------------------------------------------------------------------
__global__ void mem_mlp_kernel(const float* __restrict__ memory,
                               const float* __restrict__ w1,
                               const float* __restrict__ b1,
                               const float* __restrict__ w2,
                               const float* __restrict__ b2) {
    __shared__ float srow[C_DIM];
    __shared__ float h[C_DIM / 2];
    __shared__ float red[THREADS];
    const int m   = blockIdx.x;
    const int tid = threadIdx.x;

    srow[tid] = memory[m * C_DIM + tid];
    __syncthreads();

    if (tid < 128) {
        float acc = b1[tid];
#pragma unroll 8
        for (int c = 0; c < C_DIM; c++) acc += srow[c] * w1[c * 128 + tid];
        h[tid] = fmaxf(acc, 0.0f);
    }
    __syncthreads();

    float acc = b2[tid];
#pragma unroll 8
    for (int j = 0; j < 128; j++) acc += h[j] * w2[j * C_DIM + tid];
    acc = fmaxf(acc, 0.0f);

    red[tid] = acc * acc;
    __syncthreads();
#pragma unroll
    for (int s = 128; s > 0; s >>= 1) {
        if (tid < s) red[tid] += red[tid + s];
        __syncthreads();
    }
    const float inv = 1.0f / fmaxf(sqrtf(red[0]), 1e-12f);
    g_mem_norm[m * C_DIM + tid] = acc * inv;
}

// ---------------------------------------------------------------------------
// Kernel 2: fused per-token-tile pipeline.
//   x tile load (coalesced along hw) -> L2-normalize tokens
//   GEMM1 scores[64][512] (register 4x4 tiles, smem mem tiles)
//   softmax + hardshrink + L1 renorm (in smem)
//   att_map write (transposed, coalesced) + GEMM2 out = att @ mem_norm
// ---------------------------------------------------------------------------
__global__ __launch_bounds__(THREADS)
void fused_attn_kernel(const float* __restrict__ x,
                       float* __restrict__ out,
                       float* __restrict__ attmap) {
    extern __shared__ float smem[];
    float* scores = smem;                         // TB * SROW        (64*513)
    float* xs     = smem + TB * SROW;             // C * TB (reused as ms2 in GEMM2)
    float* msA    = xs + C_DIM * TB;              // 64 * CCHUNK
    float* invn   = msA + 64 * CCHUNK;            // TB

    const int tid = threadIdx.x;
    const int b   = blockIdx.x;
    const int n   = b >> 6;            // 64 blocks per image (4096/64 tokens)
    const int hw0 = (b & 63) << 6;

    const float* xbase = x + (size_t)n * C_DIM * HW_DIM + hw0;

    // ---- load x tile: xs[c][t], coalesced along t -------------------------
#pragma unroll 4
    for (int idx = tid; idx < C_DIM * TB; idx += THREADS) {
        const int c = idx >> 6, t = idx & 63;
        xs[c * TB + t] = xbase[(size_t)c * HW_DIM + t];
    }
    __syncthreads();

    // ---- per-token L2 norm ------------------------------------------------
    if (tid < TB) {
        float ss = 0.0f;
#pragma unroll 8
        for (int c = 0; c < C_DIM; c++) {
            const float v = xs[c * TB + tid];
            ss += v * v;
        }
        invn[tid] = 1.0f / fmaxf(sqrtf(ss), 1e-12f);
    }
    __syncthreads();
#pragma unroll 4
    for (int idx = tid; idx < C_DIM * TB; idx += THREADS) {
        xs[idx] *= invn[idx & 63];
    }
    __syncthreads();

    // ---- GEMM1: scores[t][m] = x_norm . mem_norm[m] ------------------------
    const int tIdx = tid & 15;   // 16 token groups
    const int mIdx = tid >> 4;   // 16 slot groups
    const int t0   = tIdx * 4;
    const int m0   = mIdx * 4;

    for (int mo = 0; mo < M_DIM; mo += 64) {
        float acc[4][4] = {};
        for (int co = 0; co < C_DIM; co += CCHUNK) {
            __syncthreads();
            // load msA[m][cc] (64 x 64), LDG coalesced along cc
#pragma unroll 4
            for (int idx = tid; idx < 64 * CCHUNK; idx += THREADS) {
                const int mm = idx >> 6, cc = idx & 63;
                msA[idx] = g_mem_norm[(mo + mm) * C_DIM + co + cc];
            }
            __syncthreads();
#pragma unroll 8
            for (int cc = 0; cc < CCHUNK; cc++) {
                const float4 xv = *(const float4*)&xs[(co + cc) * TB + t0];
                const float a0 = msA[(m0 + 0) * CCHUNK + cc];
                const float a1 = msA[(m0 + 1) * CCHUNK + cc];
                const float a2 = msA[(m0 + 2) * CCHUNK + cc];
                const float a3 = msA[(m0 + 3) * CCHUNK + cc];
                acc[0][0] += xv.x * a0; acc[0][1] += xv.x * a1;
                acc[0][2] += xv.x * a2; acc[0][3] += xv.x * a3;
                acc[1][0] += xv.y * a0; acc[1][1] += xv.y * a1;
                acc[1][2] += xv.y * a2; acc[1][3] += xv.y * a3;
                acc[2][0] += xv.z * a0; acc[2][1] += xv.z * a1;
                acc[2][2] += xv.z * a2; acc[2][3] += xv.z * a3;
                acc[3][0] += xv.w * a0; acc[3][1] += xv.w * a1;
                acc[3][2] += xv.w * a2; acc[3][3] += xv.w * a3;
            }
        }
#pragma unroll
        for (int i = 0; i < 4; i++)
#pragma unroll
            for (int j = 0; j < 4; j++)
                scores[(t0 + i) * SROW + mo + m0 + j] = acc[i][j];
    }
    __syncthreads();

    // ---- softmax + hardshrink + L1 renorm (one warp handles 8 tokens) ------
    const int warp = tid >> 5, lane = tid & 31;
    for (int r = 0; r < 8; r++) {
        const int t = warp * 8 + r;
        float* row = scores + t * SROW;

        float mx = -1e30f;
#pragma unroll
        for (int k = 0; k < 16; k++) mx = fmaxf(mx, row[lane + 32 * k]);
#pragma unroll
        for (int o = 16; o > 0; o >>= 1) mx = fmaxf(mx, __shfl_xor_sync(0xffffffffu, mx, o));

        float s = 0.0f;
#pragma unroll
        for (int k = 0; k < 16; k++) {
            const float v = __expf(row[lane + 32 * k] - mx);
            row[lane + 32 * k] = v;
            s += v;
        }
#pragma unroll
        for (int o = 16; o > 0; o >>= 1) s += __shfl_xor_sync(0xffffffffu, s, o);
        const float invs = 1.0f / s;   // s >= 1 always (max term)

        float as = 0.0f;
#pragma unroll
        for (int k = 0; k < 16; k++) {
            const float a = fmaxf(row[lane + 32 * k] * invs - 0.0025f, 0.0f);
            row[lane + 32 * k] = a;
            as += a;
        }
#pragma unroll
        for (int o = 16; o > 0; o >>= 1) as += __shfl_xor_sync(0xffffffffu, as, o);
        const float inva = 1.0f / fmaxf(as, 1e-12f);
#pragma unroll
        for (int k = 0; k < 16; k++) row[lane + 32 * k] *= inva;
    }
    __syncthreads();

    // ---- write att_map [n, m, h, w], coalesced along t ---------------------
    float* attb = attmap + (size_t)n * M_DIM * HW_DIM + hw0;
#pragma unroll 4
    for (int idx = tid; idx < M_DIM * TB; idx += THREADS) {
        const int t = idx & 63, mm = idx >> 6;
        attb[(size_t)mm * HW_DIM + t] = scores[t * SROW + mm];
    }

    // ---- GEMM2: out[t][c] = sum_m att[t][m] * mem_norm[m][c] ---------------
    float* ms2 = xs;                  // reuse xs region: [32][256]
    const int cIdx = tid >> 4;        // 0..15
    const int c0   = cIdx * 16;

    float acc2[4][16] = {};
    for (int mo = 0; mo < M_DIM; mo += 32) {
        __syncthreads();
#pragma unroll 4
        for (int idx = tid; idx < 32 * C_DIM; idx += THREADS) {
            const int cc = idx & 255, mk = idx >> 8;
            ms2[mk * C_DIM + cc] = g_mem_norm[(mo + mk) * C_DIM + cc];
        }
        __syncthreads();
#pragma unroll 4
        for (int mk = 0; mk < 32; mk++) {
            const float a0 = scores[(t0 + 0) * SROW + mo + mk];
            const float a1 = scores[(t0 + 1) * SROW + mo + mk];
            const float a2 = scores[(t0 + 2) * SROW + mo + mk];
            const float a3 = scores[(t0 + 3) * SROW + mo + mk];
            const float* mrow = ms2 + mk * C_DIM + c0;
#pragma unroll
            for (int j4 = 0; j4 < 4; j4++) {
                const float4 mv = *(const float4*)&mrow[j4 * 4];
                acc2[0][j4 * 4 + 0] += a0 * mv.x; acc2[0][j4 * 4 + 1] += a0 * mv.y;
                acc2[0][j4 * 4 + 2] += a0 * mv.z; acc2[0][j4 * 4 + 3] += a0 * mv.w;
                acc2[1][j4 * 4 + 0] += a1 * mv.x; acc2[1][j4 * 4 + 1] += a1 * mv.y;
                acc2[1][j4 * 4 + 2] += a1 * mv.z; acc2[1][j4 * 4 + 3] += a1 * mv.w;
                acc2[2][j4 * 4 + 0] += a2 * mv.x; acc2[2][j4 * 4 + 1] += a2 * mv.y;
                acc2[2][j4 * 4 + 2] += a2 * mv.z; acc2[2][j4 * 4 + 3] += a2 * mv.w;
                acc2[3][j4 * 4 + 0] += a3 * mv.x; acc2[3][j4 * 4 + 1] += a3 * mv.y;
                acc2[3][j4 * 4 + 2] += a3 * mv.z; acc2[3][j4 * 4 + 3] += a3 * mv.w;
            }
        }
    }

    // ---- write output [n, c, h, w]: 4 consecutive tokens -> float4 ---------
    float* ob = out + (size_t)n * C_DIM * HW_DIM + hw0;
#pragma unroll
    for (int j = 0; j < 16; j++) {
        const float4 v = make_float4(acc2[0][j], acc2[1][j], acc2[2][j], acc2[3][j]);
        *(float4*)&ob[(size_t)(c0 + j) * HW_DIM + t0] = v;
    }
}

// ---------------------------------------------------------------------------
extern "C" void kernel_launch(void* const* d_in, const int* in_sizes, int n_in,
                              void* d_out, int out_size) {
    const float* x      = (const float*)d_in[0];  // [16,256,64,64]
    const float* memory = (const float*)d_in[1];  // [512,256]
    const float* w1     = (const float*)d_in[2];  // [256,128]
    const float* b1     = (const float*)d_in[3];  // [128]
    const float* w2     = (const float*)d_in[4];  // [128,256]
    const float* b2     = (const float*)d_in[5];  // [256]

    float* out    = (float*)d_out;                              // [16,256,64,64]
    float* attmap = out + (size_t)N_IMG * C_DIM * HW_DIM;       // [16,512,64,64]

    mem_mlp_kernel<<<M_DIM, THREADS>>>(memory, w1, b1, w2, b2);

    const size_t smem_bytes =
        (size_t)(TB * SROW + C_DIM * TB + 64 * CCHUNK + TB) * sizeof(float);
    cudaFuncSetAttribute(fused_attn_kernel,
                         cudaFuncAttributeMaxDynamicSharedMemorySize,
                         (int)smem_bytes);

    const int tiles = (N_IMG * HW_DIM) / TB;  // 1024
    fused_attn_kernel<<<tiles, THREADS, smem_bytes>>>(x, out, attmap);
}